// round 4
// baseline (speedup 1.0000x reference)
#include <cuda_runtime.h>
#include <math.h>

// ---------------- scratch (static device globals; no allocation) ----------------
__device__ float g_part1[1024 * 800];          // gemm1 partials: [chunk][r*100+j]
__device__ float g_tmp1[800];                  // (8,100) row-major r*100+j
__device__ float g_bn[32];                     // boxNew (8,4)
__device__ float g_feat[8 * 24576];            // pooled features (B, 3*64*128)
__device__ float g_part2[7 * 128 * 8 * 128];   // head partials: [k][ch][r][h]

// ---------------- stage 1: xf(8x65536) @ wr2_w1(65536x100), split-K ----------------
__global__ void __launch_bounds__(128) k_gemm1_part(const float* __restrict__ x3,
                                                    const float* __restrict__ w1) {
    __shared__ __align__(16) float xs[8 * 64];
    __shared__ float red[4 * 800];
    const int bx = blockIdx.x;
    const int k0 = bx * 64;
    const int tid = threadIdx.x;

    const float4* x4 = (const float4*)x3;
    float4* xs4 = (float4*)xs;
    {
        int r = tid >> 4, q = tid & 15;
        xs4[tid] = x4[r * 16384 + bx * 16 + q];
    }
    __syncthreads();

    if (tid < 100) {
        const int ks = tid / 25;
        const int j4 = tid - ks * 25;
        const float4* w4 = (const float4*)w1;
        float acc[8][4] = {};
#pragma unroll
        for (int t = 0; t < 16; t++) {
            int kk = ks + 4 * t;
            float4 wv = w4[(size_t)(k0 + kk) * 25 + j4];
#pragma unroll
            for (int r = 0; r < 8; r++) {
                float f = xs[r * 64 + kk];
                acc[r][0] = fmaf(f, wv.x, acc[r][0]);
                acc[r][1] = fmaf(f, wv.y, acc[r][1]);
                acc[r][2] = fmaf(f, wv.z, acc[r][2]);
                acc[r][3] = fmaf(f, wv.w, acc[r][3]);
            }
        }
#pragma unroll
        for (int jj = 0; jj < 4; jj++)
#pragma unroll
            for (int r = 0; r < 8; r++)
                red[ks * 800 + r * 100 + j4 * 4 + jj] = acc[r][jj];
    }
    __syncthreads();
    for (int t = tid; t < 800; t += 128) {
        float s = red[t] + red[800 + t] + red[1600 + t] + red[2400 + t];
        g_part1[(size_t)bx * 800 + t] = s;   // coalesced, layout [chunk][r*100+j]
    }
}

// 25 blocks x 256 thr: output o = bx*32 + lane (o = r*100+j), 8 chunk phases/block.
__global__ void __launch_bounds__(256) k_reduce_g1(const float* __restrict__ b1) {
    __shared__ float red[256];
    const int tid = threadIdx.x;
    const int o = blockIdx.x * 32 + (tid & 31);
    const int cq = tid >> 5;
    float s = 0.f;
#pragma unroll 8
    for (int q = 0; q < 128; q++) s += g_part1[(size_t)(cq + 8 * q) * 800 + o];
    red[tid] = s;
    __syncthreads();
    if (tid < 32) {
        int oo = blockIdx.x * 32 + tid;
        float t = red[tid];
#pragma unroll
        for (int c = 1; c < 8; c++) t += red[c * 32 + tid];
        g_tmp1[oo] = t + b1[oo % 100];
    }
}

// ---------------- stage 2: tiny MLP -> boxLoc -> boxNew, one block per batch row ----
__global__ void __launch_bounds__(128) k_mlp_box(const float* __restrict__ w2,
                                                 const float* __restrict__ b2,
                                                 const float* __restrict__ w3,
                                                 const float* __restrict__ b3) {
    __shared__ __align__(16) float w2s[10000];
    __shared__ float t1[100], t2[104], bl[4];
    const int b = blockIdx.x;
    const int tid = threadIdx.x;

    if (tid < 100) t1[tid] = g_tmp1[b * 100 + tid];
    const float4* w24 = (const float4*)w2;
    float4* w2s4 = (float4*)w2s;
    for (int t = tid; t < 2500; t += 128) w2s4[t] = w24[t];
    __syncthreads();

    if (tid < 100) {
        float acc = b2[tid];
#pragma unroll 4
        for (int i = 0; i < 100; i++) acc = fmaf(t1[i], w2s[i * 100 + tid], acc);
        t2[tid] = acc;
    }
    __syncthreads();
    if (tid < 4) {
        float acc = b3[tid];
#pragma unroll 4
        for (int i = 0; i < 100; i++) acc = fmaf(t2[i], w3[i * 4 + tid], acc);
        bl[tid] = acc;
    }
    __syncthreads();
    if (tid < 4) {
        float v;
        if (tid == 0)      v = bl[0] - 0.5f * bl[2];
        else if (tid == 1) v = bl[1] - 0.5f * bl[3];
        else if (tid == 2) v = bl[0] + 0.5f * bl[2];
        else               v = bl[1] + 0.5f * bl[3];
        g_bn[b * 4 + tid] = fminf(fmaxf(v, 0.0f), 1.0f);
    }
}

// ---------------- stage 3: ROI adaptive max-pool, flat coalesced column scan -------
// 1536 blocks (s,b,c), 128 thr. Pass A: thread per column; ONE flat y-loop over
// the box (coalesced across lanes, loads independent -> high MLP), emitting
// per-row-bin column maxes at uniform bin boundaries (h identical across block).
// Handles torch adaptive-bin 1-row overlap by seeding next bin from current row.
// Pass B: thread per (i,j) bin maxes over smem columns.
__global__ void __launch_bounds__(128) k_roi(const float* __restrict__ x1p,
                                             const float* __restrict__ x2p,
                                             const float* __restrict__ x3p) {
    __shared__ float cm[16 * 128];
    const int bx = blockIdx.x;
    const int s = bx >> 9;
    const int rem = bx & 511;
    const int b = rem >> 6, c = rem & 63;
    const int HW = 128 >> s;
    const float* xp = (s == 0) ? x1p : (s == 1) ? x2p : x3p;

    const float Sf = (float)HW;
    const int X1 = (int)floorf(g_bn[b * 4 + 0] * Sf);
    const int Y1 = (int)floorf(g_bn[b * 4 + 1] * Sf);
    const int X2 = (int)floorf(g_bn[b * 4 + 2] * Sf);
    const int Y2 = (int)floorf(g_bn[b * 4 + 3] * Sf);
    const bool valid = (X2 < HW) && (Y2 < HW) && (X2 > X1) && (Y2 > Y1);

    const int tid = threadIdx.x;
    float* gout = &g_feat[b * 24576 + (s * 64 + c) * 128];
    if (!valid) { gout[tid] = 0.f; return; }

    const int h = Y2 - Y1 + 1, w = X2 - X1 + 1;
    const float* base = xp + ((size_t)(b * 64 + c) * HW + Y1) * HW + X1;

    if (tid < w) {
        float m = -3.0e38f;
        int bin = 0;
        int hi = (h + 15) >> 4;          // hi_0 = ceil(h/16)
#pragma unroll 2
        for (int y = 0; y < h; y++) {
            float v = base[(size_t)y * HW + tid];
            m = fmaxf(m, v);
            if (y + 1 == hi) {           // uniform across block
                cm[bin * 128 + tid] = m;
                for (;;) {
                    bin++;
                    if (bin >= 16) break;
                    hi = ((bin + 1) * h + 15) >> 4;
                    int lo = (bin * h) >> 4;
                    m = (lo <= y) ? v : -3.0e38f;   // 1-row bin overlap
                    if (y + 1 == hi) { cm[bin * 128 + tid] = m; continue; }
                    break;
                }
            }
        }
    }
    __syncthreads();
    const int i = tid >> 3, j = tid & 7;
    const int lo = (j * w) >> 3, hi2 = ((j + 1) * w + 7) >> 3;
    float m = -3.0e38f;
    for (int x = lo; x < hi2; x++) m = fmaxf(m, cm[i * 128 + x]);
    gout[tid] = m;
}

// ---------------- stage 4: feat(8x24576) @ head_w1[k](24576x128), split-K x7 --------
__global__ void __launch_bounds__(256) k_head_part(const float* __restrict__ hw) {
    __shared__ __align__(16) float fs[8 * 192];
    __shared__ __align__(16) float red[8 * 1024];
    const int bx = blockIdx.x;
    const int k = bx >> 7, ch = bx & 127;
    const int d0 = ch * 192;
    const int tid = threadIdx.x;

    const float4* f4 = (const float4*)g_feat;
    float4* fs4 = (float4*)fs;
    for (int t = tid; t < 384; t += 256) {
        int r = t / 48, q = t - r * 48;
        fs4[t] = f4[r * 6144 + ch * 48 + q];
    }
    __syncthreads();

    const int wq = tid >> 5, lane = tid & 31;
    const float4* w4 = (const float4*)hw;
    const size_t wbase = ((size_t)k * 24576 + d0 + wq * 24) * 32 + lane;
    float acc[8][4] = {};
#pragma unroll
    for (int dd = 0; dd < 24; dd++) {
        float4 wv = w4[wbase + (size_t)dd * 32];
        const int fi = wq * 24 + dd;
#pragma unroll
        for (int r = 0; r < 8; r++) {
            float f = fs[r * 192 + fi];
            acc[r][0] = fmaf(f, wv.x, acc[r][0]);
            acc[r][1] = fmaf(f, wv.y, acc[r][1]);
            acc[r][2] = fmaf(f, wv.z, acc[r][2]);
            acc[r][3] = fmaf(f, wv.w, acc[r][3]);
        }
    }
    float* myred = red + wq * 1024;
#pragma unroll
    for (int r = 0; r < 8; r++) {
        float4 v = make_float4(acc[r][0], acc[r][1], acc[r][2], acc[r][3]);
        *(float4*)&myred[r * 128 + lane * 4] = v;
    }
    __syncthreads();
    float4 sv = *(const float4*)&red[tid * 4];
#pragma unroll
    for (int w = 1; w < 8; w++) {
        float4 t4 = *(const float4*)&red[w * 1024 + tid * 4];
        sv.x += t4.x; sv.y += t4.y; sv.z += t4.z; sv.w += t4.w;
    }
    const int r = tid >> 5, hcol = (tid & 31) * 4;
    *(float4*)&g_part2[(((size_t)k * 128 + ch) * 8 + r) * 128 + hcol] = sv;
}

// ---------------- stage 5: reduce + bias + relu + output heads (fused) --------------
__global__ void __launch_bounds__(128) k_head_final(
        const float* __restrict__ hb,
        const float* __restrict__ wp, const float* __restrict__ bp,
        const float* __restrict__ wa, const float* __restrict__ ba,
        const float* __restrict__ wad, const float* __restrict__ bad,
        float* __restrict__ out) {
    __shared__ float hs[128];
    const int kb = blockIdx.x;
    const int k = kb >> 3, b = kb & 7;
    const int tid = threadIdx.x;

    float s = 0.f;
#pragma unroll 8
    for (int ch = 0; ch < 128; ch++)
        s += g_part2[(((size_t)k * 128 + ch) * 8 + b) * 128 + tid];
    s += hb[k * 128 + tid];
    hs[tid] = fmaxf(s, 0.f);
    __syncthreads();

    int O, off;
    const float *Wk, *Bk;
    if (k == 0)      { O = 38; Wk = wp; Bk = bp; off = 0; }
    else if (k == 1) { O = 25; Wk = wa; Bk = ba; off = 304; }
    else             { O = 35; Wk = wad + (k - 2) * 128 * 35; Bk = bad + (k - 2) * 35;
                       off = 504 + (k - 2) * 280; }
    if (tid < O) {
        float acc = Bk[tid];
#pragma unroll 4
        for (int h = 0; h < 128; h++) acc = fmaf(hs[h], Wk[h * O + tid], acc);
        out[off + b * O + tid] = acc;
    }
}

// ---------------- launch ----------------
extern "C" void kernel_launch(void* const* d_in, const int* in_sizes, int n_in,
                              void* d_out, int out_size) {
    (void)in_sizes; (void)n_in; (void)out_size;
    const float* x1 = (const float*)d_in[0];
    const float* x2 = (const float*)d_in[1];
    const float* x3 = (const float*)d_in[2];
    const float* w1 = (const float*)d_in[5];
    const float* b1 = (const float*)d_in[6];
    const float* w2 = (const float*)d_in[7];
    const float* b2 = (const float*)d_in[8];
    const float* w3 = (const float*)d_in[9];
    const float* b3 = (const float*)d_in[10];
    const float* hw = (const float*)d_in[11];
    const float* hb = (const float*)d_in[12];
    const float* wp = (const float*)d_in[13];
    const float* bp = (const float*)d_in[14];
    const float* wa = (const float*)d_in[15];
    const float* ba = (const float*)d_in[16];
    const float* wad = (const float*)d_in[17];
    const float* bad = (const float*)d_in[18];
    float* out = (float*)d_out;

    k_gemm1_part<<<1024, 128>>>(x3, w1);
    k_reduce_g1<<<25, 256>>>(b1);
    k_mlp_box<<<8, 128>>>(w2, b2, w3, b3);
    k_roi<<<1536, 128>>>(x1, x2, x3);
    k_head_part<<<896, 256>>>(hw);
    k_head_final<<<56, 128>>>(hb, wp, bp, wa, ba, wad, bad, out);
}

// round 5
// speedup vs baseline: 1.2843x; 1.2843x over previous
#include <cuda_runtime.h>
#include <math.h>

// ---------------- scratch (static device globals; no allocation) ----------------
__device__ float g_part1[1024 * 800];          // gemm1 partials: [chunk][r*100+j]
__device__ float g_bn[32];                     // boxNew (8,4)
__device__ float g_feat[8 * 24576];            // pooled features (B, 3*64*128)
__device__ float g_part2[7 * 128 * 8 * 128];   // head partials: [k][ch][r][h]

// ---------------- stage 1: xf(8x65536) @ wr2_w1(65536x100), split-K ----------------
__global__ void __launch_bounds__(128) k_gemm1_part(const float* __restrict__ x3,
                                                    const float* __restrict__ w1) {
    __shared__ __align__(16) float xs[8 * 64];
    __shared__ float red[4 * 800];
    const int bx = blockIdx.x;
    const int k0 = bx * 64;
    const int tid = threadIdx.x;

    const float4* x4 = (const float4*)x3;
    float4* xs4 = (float4*)xs;
    {
        int r = tid >> 4, q = tid & 15;
        xs4[tid] = x4[r * 16384 + bx * 16 + q];
    }
    __syncthreads();

    if (tid < 100) {
        const int ks = tid / 25;
        const int j4 = tid - ks * 25;
        const float4* w4 = (const float4*)w1;
        float acc[8][4] = {};
#pragma unroll
        for (int t = 0; t < 16; t++) {
            int kk = ks + 4 * t;
            float4 wv = w4[(size_t)(k0 + kk) * 25 + j4];
#pragma unroll
            for (int r = 0; r < 8; r++) {
                float f = xs[r * 64 + kk];
                acc[r][0] = fmaf(f, wv.x, acc[r][0]);
                acc[r][1] = fmaf(f, wv.y, acc[r][1]);
                acc[r][2] = fmaf(f, wv.z, acc[r][2]);
                acc[r][3] = fmaf(f, wv.w, acc[r][3]);
            }
        }
#pragma unroll
        for (int jj = 0; jj < 4; jj++)
#pragma unroll
            for (int r = 0; r < 8; r++)
                red[ks * 800 + r * 100 + j4 * 4 + jj] = acc[r][jj];
    }
    __syncthreads();
    for (int t = tid; t < 800; t += 128) {
        float s = red[t] + red[800 + t] + red[1600 + t] + red[2400 + t];
        g_part1[(size_t)bx * 800 + t] = s;   // coalesced, layout [chunk][r*100+j]
    }
}

// ---------------- stage 2 (fused): chunk-reduce + MLP + box transform ----------------
// 8 blocks (one per batch row) x 256 thr. Reduce phase: 200 threads, 2 chunk
// phases of 512, lanes j..j+31 coalesced per chunk. Then 100x100 layer, 100x4
// layer, postfix transform + clip.
__global__ void __launch_bounds__(256) k_box(const float* __restrict__ b1,
                                             const float* __restrict__ w2,
                                             const float* __restrict__ b2,
                                             const float* __restrict__ w3,
                                             const float* __restrict__ b3) {
    __shared__ __align__(16) float w2s[10000];
    __shared__ float t1r[2][100];
    __shared__ float t1[100], t2[104], bl[4];
    const int b = blockIdx.x;
    const int tid = threadIdx.x;

    const float4* w24 = (const float4*)w2;
    float4* w2s4 = (float4*)w2s;
    for (int t = tid; t < 2500; t += 256) w2s4[t] = w24[t];

    if (tid < 200) {
        const int ph = tid / 100, j = tid - ph * 100;
        float s = 0.f;
        const size_t base = (size_t)ph * 512 * 800 + b * 100 + j;
#pragma unroll 8
        for (int ch = 0; ch < 512; ch++) s += g_part1[base + (size_t)ch * 800];
        t1r[ph][j] = s;
    }
    __syncthreads();
    if (tid < 100) t1[tid] = t1r[0][tid] + t1r[1][tid] + b1[tid];
    __syncthreads();

    if (tid < 100) {
        float acc = b2[tid];
#pragma unroll 4
        for (int i = 0; i < 100; i++) acc = fmaf(t1[i], w2s[i * 100 + tid], acc);
        t2[tid] = acc;
    }
    __syncthreads();
    if (tid < 4) {
        float acc = b3[tid];
#pragma unroll 4
        for (int i = 0; i < 100; i++) acc = fmaf(t2[i], w3[i * 4 + tid], acc);
        bl[tid] = acc;
    }
    __syncthreads();
    if (tid < 4) {
        float v;
        if (tid == 0)      v = bl[0] - 0.5f * bl[2];
        else if (tid == 1) v = bl[1] - 0.5f * bl[3];
        else if (tid == 2) v = bl[0] + 0.5f * bl[2];
        else               v = bl[1] + 0.5f * bl[3];
        g_bn[b * 4 + tid] = fminf(fmaxf(v, 0.0f), 1.0f);
    }
}

// ---------------- stage 3: ROI adaptive max-pool (R1 thread-per-bin, proven) --------
__global__ void k_roi(const float* __restrict__ x1p, const float* __restrict__ x2p,
                      const float* __restrict__ x3p) {
    const int bx = blockIdx.x;        // 3*8*64 = 1536
    const int s = bx >> 9;
    const int rem = bx & 511;
    const int b = rem >> 6, c = rem & 63;
    const int HW = (s == 0) ? 128 : (s == 1) ? 64 : 32;
    const float* xp = (s == 0) ? x1p : (s == 1) ? x2p : x3p;

    const float bn0 = g_bn[b * 4 + 0], bn1 = g_bn[b * 4 + 1];
    const float bn2 = g_bn[b * 4 + 2], bn3 = g_bn[b * 4 + 3];
    const float Sf = (float)HW;
    const int X1 = (int)floorf(bn0 * Sf), Y1 = (int)floorf(bn1 * Sf);
    const int X2 = (int)floorf(bn2 * Sf), Y2 = (int)floorf(bn3 * Sf);
    const bool valid = (X1 >= 0) && (Y1 >= 0) && (X2 < HW) && (Y2 < HW) && (X2 > X1) && (Y2 > Y1);

    const int tid = threadIdx.x;  // 128 = 16x8 bins
    float out = 0.0f;
    if (valid) {
        const int h = Y2 - Y1 + 1, w = X2 - X1 + 1;
        const int i = tid >> 3, j = tid & 7;
        const int lo_i = (i * h) >> 4, hi_i = ((i + 1) * h + 15) >> 4;
        const int lo_j = (j * w) >> 3, hi_j = ((j + 1) * w + 7) >> 3;
        float m = -3.0e38f;
        const float* base = xp + ((size_t)(b * 64 + c) * HW + Y1) * HW + X1;
        for (int y = lo_i; y < hi_i; y++) {
            const float* row = base + y * HW;
            for (int xx = lo_j; xx < hi_j; xx++) m = fmaxf(m, row[xx]);
        }
        out = m;
    }
    g_feat[b * 24576 + (s * 64 + c) * 128 + tid] = out;
}

// ---------------- stage 4: feat(8x24576) @ head_w1[k](24576x128), split-K x7 --------
__global__ void __launch_bounds__(256) k_head_part(const float* __restrict__ hw) {
    __shared__ __align__(16) float fs[8 * 192];
    __shared__ __align__(16) float red[8 * 1024];
    const int bx = blockIdx.x;
    const int k = bx >> 7, ch = bx & 127;
    const int d0 = ch * 192;
    const int tid = threadIdx.x;

    const float4* f4 = (const float4*)g_feat;
    float4* fs4 = (float4*)fs;
    for (int t = tid; t < 384; t += 256) {
        int r = t / 48, q = t - r * 48;
        fs4[t] = f4[r * 6144 + ch * 48 + q];
    }
    __syncthreads();

    const int wq = tid >> 5, lane = tid & 31;
    const float4* w4 = (const float4*)hw;
    const size_t wbase = ((size_t)k * 24576 + d0 + wq * 24) * 32 + lane;
    float acc[8][4] = {};
#pragma unroll
    for (int dd = 0; dd < 24; dd++) {
        float4 wv = w4[wbase + (size_t)dd * 32];
        const int fi = wq * 24 + dd;
#pragma unroll
        for (int r = 0; r < 8; r++) {
            float f = fs[r * 192 + fi];
            acc[r][0] = fmaf(f, wv.x, acc[r][0]);
            acc[r][1] = fmaf(f, wv.y, acc[r][1]);
            acc[r][2] = fmaf(f, wv.z, acc[r][2]);
            acc[r][3] = fmaf(f, wv.w, acc[r][3]);
        }
    }
    float* myred = red + wq * 1024;
#pragma unroll
    for (int r = 0; r < 8; r++) {
        float4 v = make_float4(acc[r][0], acc[r][1], acc[r][2], acc[r][3]);
        *(float4*)&myred[r * 128 + lane * 4] = v;
    }
    __syncthreads();
    float4 sv = *(const float4*)&red[tid * 4];
#pragma unroll
    for (int w = 1; w < 8; w++) {
        float4 t4 = *(const float4*)&red[w * 1024 + tid * 4];
        sv.x += t4.x; sv.y += t4.y; sv.z += t4.z; sv.w += t4.w;
    }
    const int r = tid >> 5, hcol = (tid & 31) * 4;
    *(float4*)&g_part2[(((size_t)k * 128 + ch) * 8 + r) * 128 + hcol] = sv;
}

// ---------------- stage 5: reduce + bias + relu + output heads (fused) --------------
__global__ void __launch_bounds__(128) k_head_final(
        const float* __restrict__ hb,
        const float* __restrict__ wp, const float* __restrict__ bp,
        const float* __restrict__ wa, const float* __restrict__ ba,
        const float* __restrict__ wad, const float* __restrict__ bad,
        float* __restrict__ out) {
    __shared__ float hs[128];
    const int kb = blockIdx.x;
    const int k = kb >> 3, b = kb & 7;
    const int tid = threadIdx.x;

    float s = 0.f;
#pragma unroll 8
    for (int ch = 0; ch < 128; ch++)
        s += g_part2[(((size_t)k * 128 + ch) * 8 + b) * 128 + tid];
    s += hb[k * 128 + tid];
    hs[tid] = fmaxf(s, 0.f);
    __syncthreads();

    int O, off;
    const float *Wk, *Bk;
    if (k == 0)      { O = 38; Wk = wp; Bk = bp; off = 0; }
    else if (k == 1) { O = 25; Wk = wa; Bk = ba; off = 304; }
    else             { O = 35; Wk = wad + (k - 2) * 128 * 35; Bk = bad + (k - 2) * 35;
                       off = 504 + (k - 2) * 280; }
    if (tid < O) {
        float acc = Bk[tid];
#pragma unroll 4
        for (int h = 0; h < 128; h++) acc = fmaf(hs[h], Wk[h * O + tid], acc);
        out[off + b * O + tid] = acc;
    }
}

// ---------------- launch ----------------
extern "C" void kernel_launch(void* const* d_in, const int* in_sizes, int n_in,
                              void* d_out, int out_size) {
    (void)in_sizes; (void)n_in; (void)out_size;
    const float* x1 = (const float*)d_in[0];
    const float* x2 = (const float*)d_in[1];
    const float* x3 = (const float*)d_in[2];
    const float* w1 = (const float*)d_in[5];
    const float* b1 = (const float*)d_in[6];
    const float* w2 = (const float*)d_in[7];
    const float* b2 = (const float*)d_in[8];
    const float* w3 = (const float*)d_in[9];
    const float* b3 = (const float*)d_in[10];
    const float* hw = (const float*)d_in[11];
    const float* hb = (const float*)d_in[12];
    const float* wp = (const float*)d_in[13];
    const float* bp = (const float*)d_in[14];
    const float* wa = (const float*)d_in[15];
    const float* ba = (const float*)d_in[16];
    const float* wad = (const float*)d_in[17];
    const float* bad = (const float*)d_in[18];
    float* out = (float*)d_out;

    k_gemm1_part<<<1024, 128>>>(x3, w1);
    k_box<<<8, 256>>>(b1, w2, b2, w3, b3);
    k_roi<<<1536, 128>>>(x1, x2, x3);
    k_head_part<<<896, 256>>>(hw);     // lands in the ncu capture slot next round
    k_head_final<<<56, 128>>>(hb, wp, bp, wa, ba, wad, bad, out);
}

// round 6
// speedup vs baseline: 1.5218x; 1.1849x over previous
#include <cuda_runtime.h>
#include <math.h>

// ---------------- scratch (static device globals; no allocation) ----------------
__device__ float g_part1[1024 * 800];          // gemm1 partials: [chunk][r*100+j]
__device__ float g_bn[32];                     // boxNew (8,4)
__device__ float g_feat[8 * 24576];            // pooled features (B, 3*64*128)
__device__ float g_part2[7 * 128 * 8 * 128];   // head partials: [k][ch][r][h]

// ---------------- stage 1: xf(8x65536) @ wr2_w1(65536x100), split-K ----------------
__global__ void __launch_bounds__(128) k_gemm1_part(const float* __restrict__ x3,
                                                    const float* __restrict__ w1) {
    __shared__ __align__(16) float xs[8 * 64];
    __shared__ float red[4 * 800];
    const int bx = blockIdx.x;
    const int k0 = bx * 64;
    const int tid = threadIdx.x;

    const float4* x4 = (const float4*)x3;
    float4* xs4 = (float4*)xs;
    {
        int r = tid >> 4, q = tid & 15;
        xs4[tid] = x4[r * 16384 + bx * 16 + q];
    }
    __syncthreads();

    if (tid < 100) {
        const int ks = tid / 25;
        const int j4 = tid - ks * 25;
        const float4* w4 = (const float4*)w1;
        float acc[8][4] = {};
#pragma unroll
        for (int t = 0; t < 16; t++) {
            int kk = ks + 4 * t;
            float4 wv = w4[(size_t)(k0 + kk) * 25 + j4];
#pragma unroll
            for (int r = 0; r < 8; r++) {
                float f = xs[r * 64 + kk];
                acc[r][0] = fmaf(f, wv.x, acc[r][0]);
                acc[r][1] = fmaf(f, wv.y, acc[r][1]);
                acc[r][2] = fmaf(f, wv.z, acc[r][2]);
                acc[r][3] = fmaf(f, wv.w, acc[r][3]);
            }
        }
#pragma unroll
        for (int jj = 0; jj < 4; jj++)
#pragma unroll
            for (int r = 0; r < 8; r++)
                red[ks * 800 + r * 100 + j4 * 4 + jj] = acc[r][jj];
    }
    __syncthreads();
    for (int t = tid; t < 800; t += 128) {
        float s = red[t] + red[800 + t] + red[1600 + t] + red[2400 + t];
        g_part1[(size_t)bx * 800 + t] = s;   // coalesced, layout [chunk][r*100+j]
    }
}

// ---------------- stage 2 (fused): chunk-reduce + MLP + box transform ----------------
__global__ void __launch_bounds__(256) k_box(const float* __restrict__ b1,
                                             const float* __restrict__ w2,
                                             const float* __restrict__ b2,
                                             const float* __restrict__ w3,
                                             const float* __restrict__ b3) {
    __shared__ __align__(16) float w2s[10000];
    __shared__ float t1r[2][100];
    __shared__ float t1[100], t2[104], bl[4];
    const int b = blockIdx.x;
    const int tid = threadIdx.x;

    const float4* w24 = (const float4*)w2;
    float4* w2s4 = (float4*)w2s;
    for (int t = tid; t < 2500; t += 256) w2s4[t] = w24[t];

    if (tid < 200) {
        const int ph = tid / 100, j = tid - ph * 100;
        float s = 0.f;
        const size_t base = (size_t)ph * 512 * 800 + b * 100 + j;
#pragma unroll 16
        for (int ch = 0; ch < 512; ch++) s += g_part1[base + (size_t)ch * 800];
        t1r[ph][j] = s;
    }
    __syncthreads();
    if (tid < 100) t1[tid] = t1r[0][tid] + t1r[1][tid] + b1[tid];
    __syncthreads();

    if (tid < 100) {
        float acc = b2[tid];
#pragma unroll 4
        for (int i = 0; i < 100; i++) acc = fmaf(t1[i], w2s[i * 100 + tid], acc);
        t2[tid] = acc;
    }
    __syncthreads();
    if (tid < 4) {
        float acc = b3[tid];
#pragma unroll 4
        for (int i = 0; i < 100; i++) acc = fmaf(t2[i], w3[i * 4 + tid], acc);
        bl[tid] = acc;
    }
    __syncthreads();
    if (tid < 4) {
        float v;
        if (tid == 0)      v = bl[0] - 0.5f * bl[2];
        else if (tid == 1) v = bl[1] - 0.5f * bl[3];
        else if (tid == 2) v = bl[0] + 0.5f * bl[2];
        else               v = bl[1] + 0.5f * bl[3];
        g_bn[b * 4 + tid] = fminf(fmaxf(v, 0.0f), 1.0f);
    }
}

// ---------------- stage 3: ROI adaptive max-pool (thread-per-bin, proven) -----------
__global__ void k_roi(const float* __restrict__ x1p, const float* __restrict__ x2p,
                      const float* __restrict__ x3p) {
    const int bx = blockIdx.x;        // 3*8*64 = 1536
    const int s = bx >> 9;
    const int rem = bx & 511;
    const int b = rem >> 6, c = rem & 63;
    const int HW = (s == 0) ? 128 : (s == 1) ? 64 : 32;
    const float* xp = (s == 0) ? x1p : (s == 1) ? x2p : x3p;

    const float Sf = (float)HW;
    const int X1 = (int)floorf(g_bn[b * 4 + 0] * Sf), Y1 = (int)floorf(g_bn[b * 4 + 1] * Sf);
    const int X2 = (int)floorf(g_bn[b * 4 + 2] * Sf), Y2 = (int)floorf(g_bn[b * 4 + 3] * Sf);
    const bool valid = (X2 < HW) && (Y2 < HW) && (X2 > X1) && (Y2 > Y1);

    const int tid = threadIdx.x;  // 128 = 16x8 bins
    float out = 0.0f;
    if (valid) {
        const int h = Y2 - Y1 + 1, w = X2 - X1 + 1;
        const int i = tid >> 3, j = tid & 7;
        const int lo_i = (i * h) >> 4, hi_i = ((i + 1) * h + 15) >> 4;
        const int lo_j = (j * w) >> 3, hi_j = ((j + 1) * w + 7) >> 3;
        float m = -3.0e38f;
        const float* base = xp + ((size_t)(b * 64 + c) * HW + Y1) * HW + X1;
        for (int y = lo_i; y < hi_i; y++) {
            const float* row = base + y * HW;
            for (int xx = lo_j; xx < hi_j; xx++) m = fmaxf(m, row[xx]);
        }
        out = m;
    }
    g_feat[b * 24576 + (s * 64 + c) * 128 + tid] = out;
}

// ---------------- stage 4: feat(8x24576) @ head_w1[k](24576x128), split-K x7 --------
// 896 blocks, 256 thr. Two-phase in-place cross-warp reduce: red = 16KB.
// smem total 22.5KB -> 8 blocks/SM (full occupancy), whole grid in one wave.
__global__ void __launch_bounds__(256) k_head_part(const float* __restrict__ hw) {
    __shared__ __align__(16) float fs[8 * 192];
    __shared__ __align__(16) float red[4 * 1024];
    const int bx = blockIdx.x;
    const int k = bx >> 7, ch = bx & 127;
    const int d0 = ch * 192;
    const int tid = threadIdx.x;

    const float4* f4 = (const float4*)g_feat;
    float4* fs4 = (float4*)fs;
    for (int t = tid; t < 384; t += 256) {
        int r = t / 48, q = t - r * 48;
        fs4[t] = f4[r * 6144 + ch * 48 + q];
    }
    __syncthreads();

    const int wq = tid >> 5, lane = tid & 31;
    const float4* w4 = (const float4*)hw;
    const size_t wbase = ((size_t)k * 24576 + d0 + wq * 24) * 32 + lane;
    float acc[8][4] = {};
#pragma unroll
    for (int dd = 0; dd < 24; dd++) {
        float4 wv = w4[wbase + (size_t)dd * 32];
        const int fi = wq * 24 + dd;
#pragma unroll
        for (int r = 0; r < 8; r++) {
            float f = fs[r * 192 + fi];
            acc[r][0] = fmaf(f, wv.x, acc[r][0]);
            acc[r][1] = fmaf(f, wv.y, acc[r][1]);
            acc[r][2] = fmaf(f, wv.z, acc[r][2]);
            acc[r][3] = fmaf(f, wv.w, acc[r][3]);
        }
    }
    float* myred = red + (wq & 3) * 1024;
    if (wq < 4) {
#pragma unroll
        for (int r = 0; r < 8; r++)
            *(float4*)&myred[r * 128 + lane * 4] =
                make_float4(acc[r][0], acc[r][1], acc[r][2], acc[r][3]);
    }
    __syncthreads();
    if (wq >= 4) {
#pragma unroll
        for (int r = 0; r < 8; r++) {
            float4* p = (float4*)&myred[r * 128 + lane * 4];
            float4 v = *p;
            v.x += acc[r][0]; v.y += acc[r][1]; v.z += acc[r][2]; v.w += acc[r][3];
            *p = v;
        }
    }
    __syncthreads();
    float4 sv = *(const float4*)&red[tid * 4];
#pragma unroll
    for (int w = 1; w < 4; w++) {
        float4 t4 = *(const float4*)&red[w * 1024 + tid * 4];
        sv.x += t4.x; sv.y += t4.y; sv.z += t4.z; sv.w += t4.w;
    }
    const int r = tid >> 5, hcol = (tid & 31) * 4;
    *(float4*)&g_part2[(((size_t)k * 128 + ch) * 8 + r) * 128 + hcol] = sv;
}

// ---------------- stage 5: reduce + bias + relu + output heads (fused) --------------
// 56 blocks (k,b) x 512 thr. Chunk-reduce parallelized 4x with coalesced h-major
// reads; output gemm parallelized over 4 h-groups.
__global__ void __launch_bounds__(512) k_head_final(
        const float* __restrict__ hb,
        const float* __restrict__ wp, const float* __restrict__ bp,
        const float* __restrict__ wa, const float* __restrict__ ba,
        const float* __restrict__ wad, const float* __restrict__ bad,
        float* __restrict__ out) {
    __shared__ float red2[512];
    __shared__ float hs[128];
    const int kb = blockIdx.x;
    const int k = kb >> 3, b = kb & 7;
    const int tid = threadIdx.x;
    const int h = tid & 127, cp = tid >> 7;   // cp in [0,4)

    float s = 0.f;
#pragma unroll 8
    for (int q = 0; q < 32; q++) {
        int ch = cp * 32 + q;
        s += g_part2[(((size_t)k * 128 + ch) * 8 + b) * 128 + h];
    }
    red2[tid] = s;
    __syncthreads();
    if (tid < 128) {
        float v = red2[tid] + red2[tid + 128] + red2[tid + 256] + red2[tid + 384];
        hs[tid] = fmaxf(v + hb[k * 128 + tid], 0.f);
    }
    __syncthreads();

    int O, off;
    const float *Wk, *Bk;
    if (k == 0)      { O = 38; Wk = wp; Bk = bp; off = 0; }
    else if (k == 1) { O = 25; Wk = wa; Bk = ba; off = 304; }
    else             { O = 35; Wk = wad + (k - 2) * 128 * 35; Bk = bad + (k - 2) * 35;
                       off = 504 + (k - 2) * 280; }
    const int o = tid & 127, grp = tid >> 7;
    if (o < O) {
        float acc = 0.f;
#pragma unroll 4
        for (int hh = grp * 32; hh < grp * 32 + 32; hh++)
            acc = fmaf(hs[hh], Wk[hh * O + o], acc);
        red2[grp * 128 + o] = acc;
    }
    __syncthreads();
    if (tid < O) {
        float acc = red2[tid] + red2[128 + tid] + red2[256 + tid] + red2[384 + tid];
        out[off + b * O + tid] = acc + Bk[tid];
    }
}

// ---------------- launch ----------------
extern "C" void kernel_launch(void* const* d_in, const int* in_sizes, int n_in,
                              void* d_out, int out_size) {
    (void)in_sizes; (void)n_in; (void)out_size;
    const float* x1 = (const float*)d_in[0];
    const float* x2 = (const float*)d_in[1];
    const float* x3 = (const float*)d_in[2];
    const float* w1 = (const float*)d_in[5];
    const float* b1 = (const float*)d_in[6];
    const float* w2 = (const float*)d_in[7];
    const float* b2 = (const float*)d_in[8];
    const float* w3 = (const float*)d_in[9];
    const float* b3 = (const float*)d_in[10];
    const float* hw = (const float*)d_in[11];
    const float* hb = (const float*)d_in[12];
    const float* wp = (const float*)d_in[13];
    const float* bp = (const float*)d_in[14];
    const float* wa = (const float*)d_in[15];
    const float* ba = (const float*)d_in[16];
    const float* wad = (const float*)d_in[17];
    const float* bad = (const float*)d_in[18];
    float* out = (float*)d_out;

    k_gemm1_part<<<1024, 128>>>(x3, w1);
    k_box<<<8, 256>>>(b1, w2, b2, w3, b3);
    k_roi<<<1536, 128>>>(x1, x2, x3);
    k_head_part<<<896, 256>>>(hw);
    k_head_final<<<56, 512>>>(hb, wp, bp, wa, ba, wad, bad, out);
}

// round 7
// speedup vs baseline: 1.6070x; 1.0560x over previous
#include <cuda_runtime.h>
#include <math.h>

// ---------------- scratch (static device globals; no allocation) ----------------
__device__ float g_part1[1024 * 800];          // gemm1 partials: [chunk][r*100+j]
__device__ float g_tmp1[800];                  // (8,100): o = r*100+j
__device__ float g_bn[32];                     // boxNew (8,4)
__device__ float g_feat[8 * 24576];            // pooled features (B, 3*64*128)
__device__ float g_part2[7 * 128 * 8 * 128];   // head partials: [k][ch][r][h]

// ---------------- stage 1: xf(8x65536) @ wr2_w1(65536x100), split-K ----------------
__global__ void __launch_bounds__(128) k_gemm1_part(const float* __restrict__ x3,
                                                    const float* __restrict__ w1) {
    __shared__ __align__(16) float xs[8 * 64];
    __shared__ float red[4 * 800];
    const int bx = blockIdx.x;
    const int k0 = bx * 64;
    const int tid = threadIdx.x;

    const float4* x4 = (const float4*)x3;
    float4* xs4 = (float4*)xs;
    {
        int r = tid >> 4, q = tid & 15;
        xs4[tid] = x4[r * 16384 + bx * 16 + q];
    }
    __syncthreads();

    if (tid < 100) {
        const int ks = tid / 25;
        const int j4 = tid - ks * 25;
        const float4* w4 = (const float4*)w1;
        float acc[8][4] = {};
#pragma unroll
        for (int t = 0; t < 16; t++) {
            int kk = ks + 4 * t;
            float4 wv = w4[(size_t)(k0 + kk) * 25 + j4];
#pragma unroll
            for (int r = 0; r < 8; r++) {
                float f = xs[r * 64 + kk];
                acc[r][0] = fmaf(f, wv.x, acc[r][0]);
                acc[r][1] = fmaf(f, wv.y, acc[r][1]);
                acc[r][2] = fmaf(f, wv.z, acc[r][2]);
                acc[r][3] = fmaf(f, wv.w, acc[r][3]);
            }
        }
#pragma unroll
        for (int jj = 0; jj < 4; jj++)
#pragma unroll
            for (int r = 0; r < 8; r++)
                red[ks * 800 + r * 100 + j4 * 4 + jj] = acc[r][jj];
    }
    __syncthreads();
    for (int t = tid; t < 800; t += 128) {
        float s = red[t] + red[800 + t] + red[1600 + t] + red[2400 + t];
        g_part1[(size_t)bx * 800 + t] = s;
    }
}

// ---------------- stage 1b: wide coalesced chunk reduce (25 blocks x 256) -----------
__global__ void __launch_bounds__(256) k_reduce_g1(const float* __restrict__ b1) {
    __shared__ float red[256];
    const int tid = threadIdx.x;
    const int o = blockIdx.x * 32 + (tid & 31);
    const int cq = tid >> 5;
    float s = 0.f;
#pragma unroll 8
    for (int q = 0; q < 128; q++) s += g_part1[(size_t)(cq + 8 * q) * 800 + o];
    red[tid] = s;
    __syncthreads();
    if (tid < 32) {
        int oo = blockIdx.x * 32 + tid;
        float t = red[tid];
#pragma unroll
        for (int c = 1; c < 8; c++) t += red[c * 32 + tid];
        g_tmp1[oo] = t + b1[oo % 100];
    }
}

// ---------------- stage 2: MLP + box transform only (8 blocks) ----------------------
__global__ void __launch_bounds__(128) k_box(const float* __restrict__ w2,
                                             const float* __restrict__ b2,
                                             const float* __restrict__ w3,
                                             const float* __restrict__ b3) {
    __shared__ __align__(16) float w2s[10000];
    __shared__ float t1[100], t2[104], bl[4];
    const int b = blockIdx.x;
    const int tid = threadIdx.x;

    if (tid < 100) t1[tid] = g_tmp1[b * 100 + tid];
    const float4* w24 = (const float4*)w2;
    float4* w2s4 = (float4*)w2s;
    for (int t = tid; t < 2500; t += 128) w2s4[t] = w24[t];
    __syncthreads();

    if (tid < 100) {
        float acc = b2[tid];
#pragma unroll 4
        for (int i = 0; i < 100; i++) acc = fmaf(t1[i], w2s[i * 100 + tid], acc);
        t2[tid] = acc;
    }
    __syncthreads();
    if (tid < 4) {
        float acc = b3[tid];
#pragma unroll 4
        for (int i = 0; i < 100; i++) acc = fmaf(t2[i], w3[i * 4 + tid], acc);
        bl[tid] = acc;
    }
    __syncthreads();
    if (tid < 4) {
        float v;
        if (tid == 0)      v = bl[0] - 0.5f * bl[2];
        else if (tid == 1) v = bl[1] - 0.5f * bl[3];
        else if (tid == 2) v = bl[0] + 0.5f * bl[2];
        else               v = bl[1] + 0.5f * bl[3];
        g_bn[b * 4 + tid] = fminf(fmaxf(v, 0.0f), 1.0f);
    }
}

// ---------------- stage 3: ROI adaptive max-pool (thread-per-bin, proven) -----------
__global__ void k_roi(const float* __restrict__ x1p, const float* __restrict__ x2p,
                      const float* __restrict__ x3p) {
    const int bx = blockIdx.x;        // 1536
    const int s = bx >> 9;
    const int rem = bx & 511;
    const int b = rem >> 6, c = rem & 63;
    const int HW = (s == 0) ? 128 : (s == 1) ? 64 : 32;
    const float* xp = (s == 0) ? x1p : (s == 1) ? x2p : x3p;

    const float Sf = (float)HW;
    const int X1 = (int)floorf(g_bn[b * 4 + 0] * Sf), Y1 = (int)floorf(g_bn[b * 4 + 1] * Sf);
    const int X2 = (int)floorf(g_bn[b * 4 + 2] * Sf), Y2 = (int)floorf(g_bn[b * 4 + 3] * Sf);
    const bool valid = (X2 < HW) && (Y2 < HW) && (X2 > X1) && (Y2 > Y1);

    const int tid = threadIdx.x;  // 128 = 16x8 bins
    float out = 0.0f;
    if (valid) {
        const int h = Y2 - Y1 + 1, w = X2 - X1 + 1;
        const int i = tid >> 3, j = tid & 7;
        const int lo_i = (i * h) >> 4, hi_i = ((i + 1) * h + 15) >> 4;
        const int lo_j = (j * w) >> 3, hi_j = ((j + 1) * w + 7) >> 3;
        float m = -3.0e38f;
        const float* base = xp + ((size_t)(b * 64 + c) * HW + Y1) * HW + X1;
        for (int y = lo_i; y < hi_i; y++) {
            const float* row = base + y * HW;
            for (int xx = lo_j; xx < hi_j; xx++) m = fmaxf(m, row[xx]);
        }
        out = m;
    }
    g_feat[b * 24576 + (s * 64 + c) * 128 + tid] = out;
}

// ---------------- stage 4: head GEMM, packed f32x2 math ----------------------------
// 896 blocks, 256 thr. fs transposed to fst[fi*10 + r] (pad 10 keeps float2
// alignment & spreads banks). Batch rows packed in pairs -> fma.rn.f32x2:
// per k-step 1 LDG.128 + 4 LDS.64 + 4 packs + 16 FFMA2 (vs 8 LDS + 32 FFMA).
__global__ void __launch_bounds__(256) k_head_part(const float* __restrict__ hw) {
    __shared__ __align__(16) float fst[192 * 10];
    __shared__ __align__(16) float red[4 * 1024];
    const int bx = blockIdx.x;
    const int k = bx >> 7, ch = bx & 127;
    const int d0 = ch * 192;
    const int tid = threadIdx.x;

    if (tid < 192) {
#pragma unroll
        for (int r = 0; r < 8; r++)
            fst[tid * 10 + r] = g_feat[r * 24576 + d0 + tid];
    }
    __syncthreads();

    const int wq = tid >> 5, lane = tid & 31;
    const float4* w4 = (const float4*)hw;
    const size_t wbase = ((size_t)k * 24576 + d0 + wq * 24) * 32 + lane;
    unsigned long long acc2[4][4] = {};   // [rowpair][jcol], packed f32x2 (lo=2p, hi=2p+1)
#pragma unroll
    for (int dd = 0; dd < 24; dd++) {
        float4 wv = w4[wbase + (size_t)dd * 32];
        const int fi = wq * 24 + dd;
        unsigned long long fp[4];
#pragma unroll
        for (int p = 0; p < 4; p++)
            fp[p] = *(const unsigned long long*)&fst[fi * 10 + 2 * p];
        unsigned long long wp_[4];
        asm("mov.b64 %0, {%1, %1};" : "=l"(wp_[0]) : "f"(wv.x));
        asm("mov.b64 %0, {%1, %1};" : "=l"(wp_[1]) : "f"(wv.y));
        asm("mov.b64 %0, {%1, %1};" : "=l"(wp_[2]) : "f"(wv.z));
        asm("mov.b64 %0, {%1, %1};" : "=l"(wp_[3]) : "f"(wv.w));
#pragma unroll
        for (int p = 0; p < 4; p++)
#pragma unroll
            for (int j = 0; j < 4; j++)
                asm("fma.rn.f32x2 %0, %1, %2, %0;"
                    : "+l"(acc2[p][j]) : "l"(fp[p]), "l"(wp_[j]));
    }

    // unpack to acc[r][j]
    float acc[8][4];
#pragma unroll
    for (int p = 0; p < 4; p++)
#pragma unroll
        for (int j = 0; j < 4; j++) {
            float lo, hi;
            asm("mov.b64 {%0, %1}, %2;" : "=f"(lo), "=f"(hi) : "l"(acc2[p][j]));
            acc[2 * p][j] = lo; acc[2 * p + 1][j] = hi;
        }

    float* myred = red + (wq & 3) * 1024;
    if (wq < 4) {
#pragma unroll
        for (int r = 0; r < 8; r++)
            *(float4*)&myred[r * 128 + lane * 4] =
                make_float4(acc[r][0], acc[r][1], acc[r][2], acc[r][3]);
    }
    __syncthreads();
    if (wq >= 4) {
#pragma unroll
        for (int r = 0; r < 8; r++) {
            float4* p = (float4*)&myred[r * 128 + lane * 4];
            float4 v = *p;
            v.x += acc[r][0]; v.y += acc[r][1]; v.z += acc[r][2]; v.w += acc[r][3];
            *p = v;
        }
    }
    __syncthreads();
    float4 sv = *(const float4*)&red[tid * 4];
#pragma unroll
    for (int w = 1; w < 4; w++) {
        float4 t4 = *(const float4*)&red[w * 1024 + tid * 4];
        sv.x += t4.x; sv.y += t4.y; sv.z += t4.z; sv.w += t4.w;
    }
    const int r = tid >> 5, hcol = (tid & 31) * 4;
    *(float4*)&g_part2[(((size_t)k * 128 + ch) * 8 + r) * 128 + hcol] = sv;
}

// ---------------- stage 5: reduce + bias + relu + output heads (fused) --------------
__global__ void __launch_bounds__(512) k_head_final(
        const float* __restrict__ hb,
        const float* __restrict__ wp, const float* __restrict__ bp,
        const float* __restrict__ wa, const float* __restrict__ ba,
        const float* __restrict__ wad, const float* __restrict__ bad,
        float* __restrict__ out) {
    __shared__ float red2[512];
    __shared__ float hs[128];
    const int kb = blockIdx.x;
    const int k = kb >> 3, b = kb & 7;
    const int tid = threadIdx.x;
    const int h = tid & 127, cp = tid >> 7;

    float s = 0.f;
#pragma unroll 8
    for (int q = 0; q < 32; q++) {
        int ch = cp * 32 + q;
        s += g_part2[(((size_t)k * 128 + ch) * 8 + b) * 128 + h];
    }
    red2[tid] = s;
    __syncthreads();
    if (tid < 128) {
        float v = red2[tid] + red2[tid + 128] + red2[tid + 256] + red2[tid + 384];
        hs[tid] = fmaxf(v + hb[k * 128 + tid], 0.f);
    }
    __syncthreads();

    int O, off;
    const float *Wk, *Bk;
    if (k == 0)      { O = 38; Wk = wp; Bk = bp; off = 0; }
    else if (k == 1) { O = 25; Wk = wa; Bk = ba; off = 304; }
    else             { O = 35; Wk = wad + (k - 2) * 128 * 35; Bk = bad + (k - 2) * 35;
                       off = 504 + (k - 2) * 280; }
    const int o = tid & 127, grp = tid >> 7;
    if (o < O) {
        float acc = 0.f;
#pragma unroll 4
        for (int hh = grp * 32; hh < grp * 32 + 32; hh++)
            acc = fmaf(hs[hh], Wk[hh * O + o], acc);
        red2[grp * 128 + o] = acc;
    }
    __syncthreads();
    if (tid < O) {
        float acc = red2[tid] + red2[128 + tid] + red2[256 + tid] + red2[384 + tid];
        out[off + b * O + tid] = acc + Bk[tid];
    }
}

// ---------------- launch ----------------
extern "C" void kernel_launch(void* const* d_in, const int* in_sizes, int n_in,
                              void* d_out, int out_size) {
    (void)in_sizes; (void)n_in; (void)out_size;
    const float* x1 = (const float*)d_in[0];
    const float* x2 = (const float*)d_in[1];
    const float* x3 = (const float*)d_in[2];
    const float* w1 = (const float*)d_in[5];
    const float* b1 = (const float*)d_in[6];
    const float* w2 = (const float*)d_in[7];
    const float* b2 = (const float*)d_in[8];
    const float* w3 = (const float*)d_in[9];
    const float* b3 = (const float*)d_in[10];
    const float* hw = (const float*)d_in[11];
    const float* hb = (const float*)d_in[12];
    const float* wp = (const float*)d_in[13];
    const float* bp = (const float*)d_in[14];
    const float* wa = (const float*)d_in[15];
    const float* ba = (const float*)d_in[16];
    const float* wad = (const float*)d_in[17];
    const float* bad = (const float*)d_in[18];
    float* out = (float*)d_out;

    k_gemm1_part<<<1024, 128>>>(x3, w1);
    k_reduce_g1<<<25, 256>>>(b1);
    k_box<<<8, 128>>>(w2, b2, w3, b3);
    k_roi<<<1536, 128>>>(x1, x2, x3);
    k_head_part<<<896, 256>>>(hw);
    k_head_final<<<56, 512>>>(hb, wp, bp, wa, ba, wad, bad, out);
}

// round 8
// speedup vs baseline: 1.6846x; 1.0482x over previous
#include <cuda_runtime.h>
#include <math.h>

// ---------------- scratch (static device globals; no allocation) ----------------
__device__ float g_part1[512 * 800];           // gemm1 partials: [chunk][r*100+j]
__device__ float g_p1b[800 * 64];              // stage-A reduced: [o][cgroup]
__device__ float g_bn[32];                     // boxNew (8,4)
__device__ float g_feat[8 * 24576];            // pooled features (B, 3*64*128)
__device__ float g_part2[7 * 128 * 8 * 128];   // head partials: [k][ch][r][h]

// ---------------- stage 1: xf(8x65536) @ wr2_w1(65536x100), split-K ----------------
// 512 blocks x 128 thr; block covers 128 K-rows, 4-way in-block K-split + reduce.
__global__ void __launch_bounds__(128) k_gemm1_part(const float* __restrict__ x3,
                                                    const float* __restrict__ w1) {
    __shared__ __align__(16) float xs[8 * 128];
    __shared__ float red[4 * 800];
    const int bx = blockIdx.x;
    const int k0 = bx * 128;
    const int tid = threadIdx.x;

    const float4* x4 = (const float4*)x3;
    float4* xs4 = (float4*)xs;
#pragma unroll
    for (int t = 0; t < 2; t++) {
        int idx = tid + t * 128;
        int r = idx >> 5, q = idx & 31;
        xs4[idx] = x4[r * 16384 + bx * 32 + q];
    }
    __syncthreads();

    if (tid < 100) {
        const int ks = tid / 25;
        const int j4 = tid - ks * 25;
        const float4* w4 = (const float4*)w1;
        float acc[8][4] = {};
#pragma unroll
        for (int t = 0; t < 32; t++) {
            int kk = ks + 4 * t;
            float4 wv = w4[(size_t)(k0 + kk) * 25 + j4];
#pragma unroll
            for (int r = 0; r < 8; r++) {
                float f = xs[r * 128 + kk];
                acc[r][0] = fmaf(f, wv.x, acc[r][0]);
                acc[r][1] = fmaf(f, wv.y, acc[r][1]);
                acc[r][2] = fmaf(f, wv.z, acc[r][2]);
                acc[r][3] = fmaf(f, wv.w, acc[r][3]);
            }
        }
#pragma unroll
        for (int jj = 0; jj < 4; jj++)
#pragma unroll
            for (int r = 0; r < 8; r++)
                red[ks * 800 + r * 100 + j4 * 4 + jj] = acc[r][jj];
    }
    __syncthreads();
    for (int t = tid; t < 800; t += 128) {
        float s = red[t] + red[800 + t] + red[1600 + t] + red[2400 + t];
        g_part1[(size_t)bx * 800 + t] = s;   // coalesced
    }
}

// ---------------- stage 1b: coalesced stage-A reduce (64 blocks x 256) --------------
// Block cg sums chunk-rows [cg*8, cg*8+8) fully coalesced; writes transposed
// g_p1b[o*64+cg] (only 800 scattered floats -- negligible).
__global__ void __launch_bounds__(256) k_reduce_a() {
    const int cg = blockIdx.x;
    const int tid = threadIdx.x;
    float a0 = 0.f, a1 = 0.f, a2 = 0.f, a3 = 0.f;
    const float* base = g_part1 + (size_t)cg * 8 * 800;
#pragma unroll
    for (int q = 0; q < 8; q++) {
        const float* row = base + q * 800;
        a0 += row[tid];
        a1 += row[tid + 256];
        a2 += row[tid + 512];
        if (tid < 32) a3 += row[tid + 768];
    }
    g_p1b[(size_t)tid * 64 + cg] = a0;
    g_p1b[(size_t)(tid + 256) * 64 + cg] = a1;
    g_p1b[(size_t)(tid + 512) * 64 + cg] = a2;
    if (tid < 32) g_p1b[(size_t)(tid + 768) * 64 + cg] = a3;
}

// ---------------- stage 2: stage-B reduce + MLP + box transform (8 blocks) ----------
__global__ void __launch_bounds__(128) k_box(const float* __restrict__ b1,
                                             const float* __restrict__ w2,
                                             const float* __restrict__ b2,
                                             const float* __restrict__ w3,
                                             const float* __restrict__ b3) {
    __shared__ __align__(16) float w2s[10000];
    __shared__ float t1[100], t2[104], bl[4];
    const int b = blockIdx.x;
    const int tid = threadIdx.x;

    const float4* w24 = (const float4*)w2;
    float4* w2s4 = (float4*)w2s;
    for (int t = tid; t < 2500; t += 128) w2s4[t] = w24[t];

    if (tid < 100) {
        const float4* p = (const float4*)&g_p1b[(size_t)(b * 100 + tid) * 64];
        float s = 0.f;
#pragma unroll
        for (int q = 0; q < 16; q++) {
            float4 v = p[q];
            s += v.x + v.y + v.z + v.w;
        }
        t1[tid] = s + b1[tid];
    }
    __syncthreads();

    if (tid < 100) {
        float acc = b2[tid];
#pragma unroll 4
        for (int i = 0; i < 100; i++) acc = fmaf(t1[i], w2s[i * 100 + tid], acc);
        t2[tid] = acc;
    }
    __syncthreads();
    if (tid < 4) {
        float acc = b3[tid];
#pragma unroll 4
        for (int i = 0; i < 100; i++) acc = fmaf(t2[i], w3[i * 4 + tid], acc);
        bl[tid] = acc;
    }
    __syncthreads();
    if (tid < 4) {
        float v;
        if (tid == 0)      v = bl[0] - 0.5f * bl[2];
        else if (tid == 1) v = bl[1] - 0.5f * bl[3];
        else if (tid == 2) v = bl[0] + 0.5f * bl[2];
        else               v = bl[1] + 0.5f * bl[3];
        g_bn[b * 4 + tid] = fminf(fmaxf(v, 0.0f), 1.0f);
    }
}

// ---------------- stage 3: ROI max-pool, 2 threads per bin (y-split) ----------------
__global__ void __launch_bounds__(256) k_roi(const float* __restrict__ x1p,
                                             const float* __restrict__ x2p,
                                             const float* __restrict__ x3p) {
    __shared__ float sm[128];
    const int bx = blockIdx.x;        // 1536
    const int s = bx >> 9;
    const int rem = bx & 511;
    const int b = rem >> 6, c = rem & 63;
    const int HW = (s == 0) ? 128 : (s == 1) ? 64 : 32;
    const float* xp = (s == 0) ? x1p : (s == 1) ? x2p : x3p;

    const float Sf = (float)HW;
    const int X1 = (int)floorf(g_bn[b * 4 + 0] * Sf), Y1 = (int)floorf(g_bn[b * 4 + 1] * Sf);
    const int X2 = (int)floorf(g_bn[b * 4 + 2] * Sf), Y2 = (int)floorf(g_bn[b * 4 + 3] * Sf);
    const bool valid = (X2 < HW) && (Y2 < HW) && (X2 > X1) && (Y2 > Y1);

    const int tid = threadIdx.x;
    const int bin = tid & 127, half = tid >> 7;
    float m = -3.0e38f;
    if (valid) {
        const int h = Y2 - Y1 + 1, w = X2 - X1 + 1;
        const int i = bin >> 3, j = bin & 7;
        const int lo_i = (i * h) >> 4, hi_i = ((i + 1) * h + 15) >> 4;
        const int lo_j = (j * w) >> 3, hi_j = ((j + 1) * w + 7) >> 3;
        const int mid = (lo_i + hi_i + 1) >> 1;
        const int y0 = half ? mid : lo_i;
        const int y1 = half ? hi_i : mid;
        const float* base = xp + ((size_t)(b * 64 + c) * HW + Y1) * HW + X1;
        for (int y = y0; y < y1; y++) {
            const float* row = base + y * HW;
            for (int xx = lo_j; xx < hi_j; xx++) m = fmaxf(m, row[xx]);
        }
    }
    if (half) sm[bin] = m;
    __syncthreads();
    if (!half) {
        float out = valid ? fmaxf(m, sm[bin]) : 0.f;
        g_feat[b * 24576 + (s * 64 + c) * 128 + bin] = out;
    }
}

// ---------------- stage 4: head GEMM, packed f32x2 math ----------------------------
__global__ void __launch_bounds__(256) k_head_part(const float* __restrict__ hw) {
    __shared__ __align__(16) float fst[192 * 10];
    __shared__ __align__(16) float red[4 * 1024];
    const int bx = blockIdx.x;
    const int k = bx >> 7, ch = bx & 127;
    const int d0 = ch * 192;
    const int tid = threadIdx.x;

    if (tid < 192) {
#pragma unroll
        for (int r = 0; r < 8; r++)
            fst[tid * 10 + r] = g_feat[r * 24576 + d0 + tid];
    }
    __syncthreads();

    const int wq = tid >> 5, lane = tid & 31;
    const float4* w4 = (const float4*)hw;
    const size_t wbase = ((size_t)k * 24576 + d0 + wq * 24) * 32 + lane;
    unsigned long long acc2[4][4] = {};
#pragma unroll
    for (int dd = 0; dd < 24; dd++) {
        float4 wv = w4[wbase + (size_t)dd * 32];
        const int fi = wq * 24 + dd;
        unsigned long long fp[4];
#pragma unroll
        for (int p = 0; p < 4; p++)
            fp[p] = *(const unsigned long long*)&fst[fi * 10 + 2 * p];
        unsigned long long wp_[4];
        asm("mov.b64 %0, {%1, %1};" : "=l"(wp_[0]) : "f"(wv.x));
        asm("mov.b64 %0, {%1, %1};" : "=l"(wp_[1]) : "f"(wv.y));
        asm("mov.b64 %0, {%1, %1};" : "=l"(wp_[2]) : "f"(wv.z));
        asm("mov.b64 %0, {%1, %1};" : "=l"(wp_[3]) : "f"(wv.w));
#pragma unroll
        for (int p = 0; p < 4; p++)
#pragma unroll
            for (int j = 0; j < 4; j++)
                asm("fma.rn.f32x2 %0, %1, %2, %0;"
                    : "+l"(acc2[p][j]) : "l"(fp[p]), "l"(wp_[j]));
    }

    float acc[8][4];
#pragma unroll
    for (int p = 0; p < 4; p++)
#pragma unroll
        for (int j = 0; j < 4; j++) {
            float lo, hi;
            asm("mov.b64 {%0, %1}, %2;" : "=f"(lo), "=f"(hi) : "l"(acc2[p][j]));
            acc[2 * p][j] = lo; acc[2 * p + 1][j] = hi;
        }

    float* myred = red + (wq & 3) * 1024;
    if (wq < 4) {
#pragma unroll
        for (int r = 0; r < 8; r++)
            *(float4*)&myred[r * 128 + lane * 4] =
                make_float4(acc[r][0], acc[r][1], acc[r][2], acc[r][3]);
    }
    __syncthreads();
    if (wq >= 4) {
#pragma unroll
        for (int r = 0; r < 8; r++) {
            float4* p = (float4*)&myred[r * 128 + lane * 4];
            float4 v = *p;
            v.x += acc[r][0]; v.y += acc[r][1]; v.z += acc[r][2]; v.w += acc[r][3];
            *p = v;
        }
    }
    __syncthreads();
    float4 sv = *(const float4*)&red[tid * 4];
#pragma unroll
    for (int w = 1; w < 4; w++) {
        float4 t4 = *(const float4*)&red[w * 1024 + tid * 4];
        sv.x += t4.x; sv.y += t4.y; sv.z += t4.z; sv.w += t4.w;
    }
    const int r = tid >> 5, hcol = (tid & 31) * 4;
    *(float4*)&g_part2[(((size_t)k * 128 + ch) * 8 + r) * 128 + hcol] = sv;
}

// ---------------- stage 5: reduce + bias + relu + output heads (fused) --------------
__global__ void __launch_bounds__(512) k_head_final(
        const float* __restrict__ hb,
        const float* __restrict__ wp, const float* __restrict__ bp,
        const float* __restrict__ wa, const float* __restrict__ ba,
        const float* __restrict__ wad, const float* __restrict__ bad,
        float* __restrict__ out) {
    __shared__ float red2[512];
    __shared__ float hs[128];
    const int kb = blockIdx.x;
    const int k = kb >> 3, b = kb & 7;
    const int tid = threadIdx.x;
    const int h = tid & 127, cp = tid >> 7;

    float s = 0.f;
#pragma unroll 8
    for (int q = 0; q < 32; q++) {
        int ch = cp * 32 + q;
        s += g_part2[(((size_t)k * 128 + ch) * 8 + b) * 128 + h];
    }
    red2[tid] = s;
    __syncthreads();
    if (tid < 128) {
        float v = red2[tid] + red2[tid + 128] + red2[tid + 256] + red2[tid + 384];
        hs[tid] = fmaxf(v + hb[k * 128 + tid], 0.f);
    }
    __syncthreads();

    int O, off;
    const float *Wk, *Bk;
    if (k == 0)      { O = 38; Wk = wp; Bk = bp; off = 0; }
    else if (k == 1) { O = 25; Wk = wa; Bk = ba; off = 304; }
    else             { O = 35; Wk = wad + (k - 2) * 128 * 35; Bk = bad + (k - 2) * 35;
                       off = 504 + (k - 2) * 280; }
    const int o = tid & 127, grp = tid >> 7;
    if (o < O) {
        float acc = 0.f;
#pragma unroll 4
        for (int hh = grp * 32; hh < grp * 32 + 32; hh++)
            acc = fmaf(hs[hh], Wk[hh * O + o], acc);
        red2[grp * 128 + o] = acc;
    }
    __syncthreads();
    if (tid < O) {
        float acc = red2[tid] + red2[128 + tid] + red2[256 + tid] + red2[384 + tid];
        out[off + b * O + tid] = acc + Bk[tid];
    }
}

// ---------------- launch ----------------
extern "C" void kernel_launch(void* const* d_in, const int* in_sizes, int n_in,
                              void* d_out, int out_size) {
    (void)in_sizes; (void)n_in; (void)out_size;
    const float* x1 = (const float*)d_in[0];
    const float* x2 = (const float*)d_in[1];
    const float* x3 = (const float*)d_in[2];
    const float* w1 = (const float*)d_in[5];
    const float* b1 = (const float*)d_in[6];
    const float* w2 = (const float*)d_in[7];
    const float* b2 = (const float*)d_in[8];
    const float* w3 = (const float*)d_in[9];
    const float* b3 = (const float*)d_in[10];
    const float* hw = (const float*)d_in[11];
    const float* hb = (const float*)d_in[12];
    const float* wp = (const float*)d_in[13];
    const float* bp = (const float*)d_in[14];
    const float* wa = (const float*)d_in[15];
    const float* ba = (const float*)d_in[16];
    const float* wad = (const float*)d_in[17];
    const float* bad = (const float*)d_in[18];
    float* out = (float*)d_out;

    k_gemm1_part<<<512, 128>>>(x3, w1);
    k_reduce_a<<<64, 256>>>();
    k_box<<<8, 128>>>(b1, w2, b2, w3, b3);
    k_roi<<<1536, 256>>>(x1, x2, x3);
    k_head_part<<<896, 256>>>(hw);
    k_head_final<<<56, 512>>>(hb, wp, bp, wa, ba, wad, bad, out);
}